// round 15
// baseline (speedup 1.0000x reference)
#include <cuda_runtime.h>
#include <cuda_fp16.h>
#include <cstdint>

#define T_TOK 8192
#define D_IN  1024
#define D_OUT 1024
#define NE    8
#define TM    128
#define TN    128
#define BK    32
#define KSTAGES (D_IN / BK)          // 32
#define NST   3
#define ROWB  80                     // 32 fp16 = 64B + 16B pad (conflict-free)
#define TILEB (128 * ROWB)           // 10240
#define STGB  (2 * TILEB)            // 20480: A|B
#define OFF_STOK (NST * STGB)        // 61440
#define OFF_BIAS (OFF_STOK + 512)
#define SMEM_GEMM (OFF_BIAS + 512)
#define MAXTILES (T_TOK/TM + NE)     // 72
#define TOK_PER_BLK 32
#define GATE_BLKS (T_TOK / TOK_PER_BLK)  // 256
#define CONV_BLKS 1024

// ---------------- device scratch ----------------
__device__ float g_gate_part[GATE_BLKS * NE];
__device__ int   g_top1[T_TOK];
__device__ int   g_perm[T_TOK];
__device__ int   g_tile_e[MAXTILES];
__device__ int   g_tile_row[MAXTILES];
__device__ int   g_tile_nrows[MAXTILES];
__device__ int   g_ntiles;
__device__ int   g_done = 0;

__device__ __align__(128) __half g_xh[T_TOK * D_IN];
__device__ __align__(128) __half g_Wh[NE * D_OUT * D_IN];

// ---------------- helpers ----------------
__device__ __forceinline__ uint32_t smem_u32(const void* p) {
    return (uint32_t)__cvta_generic_to_shared(p);
}
__device__ __forceinline__ void cpa16(uint32_t dst, const void* src) {
    asm volatile("cp.async.cg.shared.global [%0], [%1], 16;\n" :: "r"(dst), "l"(src));
}
#define CP_COMMIT() asm volatile("cp.async.commit_group;" ::: "memory")
#define CP_WAIT(n)  asm volatile("cp.async.wait_group %0;" :: "n"(n) : "memory")

__device__ __forceinline__ void ldsm4(uint32_t* r, uint32_t a) {
    asm volatile("ldmatrix.sync.aligned.m8n8.x4.shared.b16 {%0,%1,%2,%3}, [%4];"
                 : "=r"(r[0]), "=r"(r[1]), "=r"(r[2]), "=r"(r[3]) : "r"(a));
}
__device__ __forceinline__ void mma_f16(float* c, const uint32_t* a, const uint32_t* b) {
    asm volatile("mma.sync.aligned.m16n8k16.row.col.f32.f16.f16.f32 "
                 "{%0,%1,%2,%3}, {%4,%5,%6,%7}, {%8,%9}, {%0,%1,%2,%3};"
                 : "+f"(c[0]), "+f"(c[1]), "+f"(c[2]), "+f"(c[3])
                 : "r"(a[0]), "r"(a[1]), "r"(a[2]), "r"(a[3]),
                   "r"(b[0]), "r"(b[1]));
}

// ---------------- fused: gate(+x convert) | We convert | tail mid ---------
__global__ void gate_conv_kernel(const float* __restrict__ x,
                                 const float* __restrict__ Wg,
                                 const float* __restrict__ bg,
                                 const float* __restrict__ We,
                                 float* __restrict__ out_aux, int has_aux) {
    int tid = threadIdx.x;

    if (blockIdx.x >= GATE_BLKS) {
        // ---- We -> fp16 convert ----
        size_t base = ((size_t)(blockIdx.x - GATE_BLKS) * 256 + tid) * 4;
        size_t stride = (size_t)CONV_BLKS * 256 * 4;
#pragma unroll
        for (int i = 0; i < 8; i++) {
            size_t idx = base + (size_t)i * stride;
            float4 v = *(const float4*)(We + idx);
            *(__half2*)(g_Wh + idx)     = __halves2half2(__float2half(v.x), __float2half(v.y));
            *(__half2*)(g_Wh + idx + 2) = __halves2half2(__float2half(v.z), __float2half(v.w));
        }
        return;
    }

    // ---- gate: 32 tokens per block, 4 per warp ----
    __shared__ float sWg[NE * D_IN];   // 32 KB; reused by the tail-mid block
    __shared__ float sSum[NE];
    __shared__ int   sLast;
    for (int i = tid; i < NE * D_IN; i += blockDim.x) sWg[i] = Wg[i];
    if (tid < NE) sSum[tid] = 0.f;
    __syncthreads();

    int lane = tid & 31, warp = tid >> 5;
#pragma unroll
    for (int tt = 0; tt < 4; tt++) {
        int t = blockIdx.x * TOK_PER_BLK + warp * 4 + tt;
        const float* xp = x + (size_t)t * D_IN;

        float acc[NE];
#pragma unroll
        for (int e = 0; e < NE; e++) acc[e] = 0.f;
        __half* oh = g_xh + (size_t)t * D_IN;
#pragma unroll
        for (int i = 0; i < 8; i++) {
            int d = lane * 4 + i * 128;
            float4 v = *(const float4*)(xp + d);
            // convert to fp16 on the fly
            *(__half2*)(oh + d)     = __halves2half2(__float2half(v.x), __float2half(v.y));
            *(__half2*)(oh + d + 2) = __halves2half2(__float2half(v.z), __float2half(v.w));
#pragma unroll
            for (int e = 0; e < NE; e++) {
                const float* wg = sWg + e * D_IN + d;
                acc[e] = fmaf(v.x, wg[0], acc[e]);
                acc[e] = fmaf(v.y, wg[1], acc[e]);
                acc[e] = fmaf(v.z, wg[2], acc[e]);
                acc[e] = fmaf(v.w, wg[3], acc[e]);
            }
        }
#pragma unroll
        for (int e = 0; e < NE; e++) {
#pragma unroll
            for (int o = 16; o; o >>= 1) acc[e] += __shfl_xor_sync(0xffffffffu, acc[e], o);
        }
        if (lane == 0) {
            float m = -1e30f; int am = 0;
#pragma unroll
            for (int e = 0; e < NE; e++) {
                acc[e] += bg[e];
                if (acc[e] > m) { m = acc[e]; am = e; }
            }
            float s = 0.f, p[NE];
#pragma unroll
            for (int e = 0; e < NE; e++) { p[e] = expf(acc[e] - m); s += p[e]; }
            float inv = 1.f / s;
            g_top1[t] = am;
#pragma unroll
            for (int e = 0; e < NE; e++) atomicAdd(&sSum[e], p[e] * inv);
        }
    }
    __syncthreads();
    if (tid < NE) g_gate_part[blockIdx.x * NE + tid] = sSum[tid];

    // ---- completion count; last block performs "mid" ----
    __threadfence();
    if (tid == 0) {
        int old = atomicAdd(&g_done, 1);
        sLast = (old == GATE_BLKS - 1);
    }
    __syncthreads();
    if (!sLast) return;
    __threadfence();

    // repurpose sWg as scratch: lcnt[256][NE] (8 KB)
    int (*lcnt)[NE] = (int(*)[NE])sWg;
    __shared__ int   hcnt[NE];
    __shared__ int   cur0[NE];
    __shared__ float ssum[NE];
    if (tid < NE) ssum[tid] = 0.f;
    __syncthreads();

    int lc[NE];
#pragma unroll
    for (int e = 0; e < NE; e++) lc[e] = 0;
    for (int t = tid; t < T_TOK; t += 256) lc[g_top1[t]]++;
#pragma unroll
    for (int e = 0; e < NE; e++) lcnt[tid][e] = lc[e];

    float ls[NE];
#pragma unroll
    for (int e = 0; e < NE; e++) ls[e] = 0.f;
    for (int j = tid; j < GATE_BLKS; j += 256) {
#pragma unroll
        for (int e = 0; e < NE; e++) ls[e] += g_gate_part[j * NE + e];
    }
#pragma unroll
    for (int e = 0; e < NE; e++) {
#pragma unroll
        for (int o = 16; o; o >>= 1) ls[e] += __shfl_xor_sync(0xffffffffu, ls[e], o);
        if ((tid & 31) == 0) atomicAdd(&ssum[e], ls[e]);
    }
    __syncthreads();

    if (tid < NE) {
        int run = 0;
        for (int i = 0; i < 256; i++) {
            int v = lcnt[i][tid];
            lcnt[i][tid] = run;
            run += v;
        }
        hcnt[tid] = run;
    }
    __syncthreads();

    if (tid == 0) {
        int off = 0, n = 0;
        for (int e = 0; e < NE; e++) {
            cur0[e] = off;
            int c = hcnt[e];
            int nt = (c + TM - 1) / TM;
            for (int j = 0; j < nt; j++) {
                g_tile_e[n] = e;
                g_tile_row[n] = off + j * TM;
                int rem = c - j * TM;
                g_tile_nrows[n] = rem < TM ? rem : TM;
                n++;
            }
            off += c;
        }
        g_ntiles = n;
        if (has_aux) {
            float s = 0.f;
            for (int e = 0; e < NE; e++) {
                float mg = ssum[e] * (float)NE / (float)T_TOK;
                s += mg * mg;
            }
            *out_aux = s / (float)NE;
        }
        g_done = 0;   // reset for next graph replay
    }
    __syncthreads();

    int ofs[NE];
#pragma unroll
    for (int e = 0; e < NE; e++) ofs[e] = cur0[e] + lcnt[tid][e];
    for (int t = tid; t < T_TOK; t += 256) {
        int e = g_top1[t];
        g_perm[ofs[e]++] = t;
    }
}

// ---------------- expert GEMM: fp16 1-pass, perm-indirect A loads --------
__global__ void __launch_bounds__(256, 2)
mma_gemm_kernel(const float* __restrict__ be, float* __restrict__ out) {
    int tile = blockIdx.y;
    if (tile >= g_ntiles) return;
    int e     = g_tile_e[tile];
    int row0  = g_tile_row[tile];
    int nrows = g_tile_nrows[tile];
    int o0    = blockIdx.x * TN;

    extern __shared__ char smem[];
    uint32_t sb = smem_u32(smem);
    int tid = threadIdx.x, l = tid & 31, wid = tid >> 5;
    int wm = wid & 3, wn = wid >> 2;

    int*   stok = (int*)(smem + OFF_STOK);
    float* bias = (float*)(smem + OFF_BIAS);
    if (tid < TM) {
        int r = tid < nrows ? tid : nrows - 1;
        stok[tid] = g_perm[row0 + r];
        bias[tid] = be[e * D_OUT + o0 + tid];
    }

    const __half* sp[4];
    uint32_t doff[4];
#pragma unroll
    for (int j = 0; j < 4; j++) {
        int c = tid + j * 256;
        int t2i = c >> 9;            // 0..1
        int row = (c >> 2) & 127;
        int kc = c & 3;
        if (t2i == 0) {
            int rr = row < nrows ? row : nrows - 1;
            sp[j] = g_xh + (size_t)g_perm[row0 + rr] * D_IN + kc * 8;
        } else {
            sp[j] = g_Wh + ((size_t)e * D_OUT + o0 + row) * D_IN + kc * 8;
        }
        doff[j] = (uint32_t)(t2i * TILEB + row * ROWB + kc * 16);
    }

    auto load_stage = [&](int buf, int k0) {
        uint32_t base = sb + buf * STGB;
#pragma unroll
        for (int j = 0; j < 4; j++) cpa16(base + doff[j], sp[j] + k0);
    };

    uint32_t aOff = (uint32_t)((wm * 32 + (l & 15)) * ROWB + ((l >> 4) & 1) * 16);
    uint32_t bOff = (uint32_t)(TILEB + (wn * 64 + (l & 7) + ((l >> 4) & 1) * 8) * ROWB +
                               ((l >> 3) & 1) * 16);

    load_stage(0, 0);  CP_COMMIT();
    load_stage(1, BK); CP_COMMIT();

    float acc[2][8][4];
#pragma unroll
    for (int mi = 0; mi < 2; mi++)
#pragma unroll
        for (int nj = 0; nj < 8; nj++)
#pragma unroll
            for (int q = 0; q < 4; q++) acc[mi][nj][q] = 0.f;

    __syncthreads();

    for (int s = 0; s < KSTAGES; s++) {
        CP_WAIT(1);
        __syncthreads();
        if (s + 2 < KSTAGES) load_stage((s + 2) % NST, (s + 2) * BK);
        CP_COMMIT();

        uint32_t stb = sb + (s % NST) * STGB;
#pragma unroll
        for (int ks = 0; ks < 2; ks++) {
            uint32_t ah[2][4], bh[4][4];
            uint32_t aB = stb + aOff + ks * 32;
            uint32_t bB = stb + bOff + ks * 32;
            ldsm4(ah[0], aB);
            ldsm4(ah[1], aB + 16 * ROWB);
#pragma unroll
            for (int np = 0; np < 4; np++)
                ldsm4(bh[np], bB + np * 16 * ROWB);
#pragma unroll
            for (int mi = 0; mi < 2; mi++)
#pragma unroll
                for (int nj = 0; nj < 8; nj++)
                    mma_f16(acc[mi][nj], ah[mi], &bh[nj >> 1][(nj & 1) * 2]);
        }
    }

    // epilogue
    int g = l >> 2, t2 = (l & 3) * 2;
#pragma unroll
    for (int mi = 0; mi < 2; mi++) {
#pragma unroll
        for (int half = 0; half < 2; half++) {
            int row = wm * 32 + mi * 16 + g + half * 8;
            if (row < nrows) {
                float* op = out + (size_t)stok[row] * D_OUT + o0;
#pragma unroll
                for (int nj = 0; nj < 8; nj++) {
                    int col = wn * 64 + nj * 8 + t2;
                    float2 v;
                    v.x = acc[mi][nj][half * 2 + 0] + bias[col];
                    v.y = acc[mi][nj][half * 2 + 1] + bias[col + 1];
                    *(float2*)(op + col) = v;
                }
            }
        }
    }
}

// ---------------- launch ----------------
extern "C" void kernel_launch(void* const* d_in, const int* in_sizes, int n_in,
                              void* d_out, int out_size) {
    const float* x  = (const float*)d_in[0];
    const float* We = (const float*)d_in[1];
    const float* be = (const float*)d_in[2];
    const float* Wg = (const float*)d_in[3];
    const float* bg = (const float*)d_in[4];
    float* out = (float*)d_out;

    cudaFuncSetAttribute(mma_gemm_kernel,
                         cudaFuncAttributeMaxDynamicSharedMemorySize, SMEM_GEMM);

    int has_aux = out_size > T_TOK * D_OUT;
    gate_conv_kernel<<<GATE_BLKS + CONV_BLKS, 256>>>(x, Wg, bg, We,
        out + (size_t)T_TOK * D_OUT, has_aux);
    dim3 grid(D_OUT / TN, MAXTILES);
    mma_gemm_kernel<<<grid, 256, SMEM_GEMM>>>(be, out);
}